// round 3
// baseline (speedup 1.0000x reference)
#include <cuda_runtime.h>
#include <cstddef>

// Ghost-cell padding with affine boundary conditions.
// arr: (4, 4096, 4096) f32 -> out: (4, 4098, 4098) f32
//
// Unified row model: orow[0]=edgeL; orow[p]=fma(fac, a[p-1], c) for p=1..4096;
// orow[4097]=edgeR. Interior rows: (fac,c)=(1,0) (exact copy), edges = axis-1
// affine ghosts. Top/bottom rows: (fac,c)=bc[axis0,side], edges = 0 corners.
//
// Load path: aligned LDG.128 of a[P..P+3] (input rows are 16B aligned),
// shifted element a[P-1] comes from the previous lane's A.w via shfl_up
// (lane 0 uses one predicated scalar load). Stores: 2x STG.64, always 8B
// aligned (row base even, P multiple of 4).

static constexpr int F  = 4;
static constexpr int NX = 4096;
static constexpr int NY = 4096;
static constexpr int PX = NX + 2;   // 4098
static constexpr int PY = NY + 2;   // 4098

static constexpr int THREADS = 512;
// Row body: P = 4*(t + i*512), i in {0,1}  ->  P in {0,4,...,4092},
// covering output positions 0..4095. Tail pair (4096, 4097) is stored by
// the last thread of iteration 1 (which already holds a[4095] in A.w).

__global__ void __launch_bounds__(THREADS)
ghost_pad_kernel(const float* __restrict__ arr,
                 const float* __restrict__ bc,   // bc_const  flat [axis*2+side]
                 const float* __restrict__ bf,   // bc_factor flat [axis*2+side]
                 float* __restrict__ out)
{
    const int row = blockIdx.x;     // 0 .. PX-1
    const int f   = blockIdx.y;     // field

    const float* __restrict__ a;
    float fac, c, edgeL, edgeR;

    if (row == 0) {
        // top ghost row: affine of arr[f, 0, :], corners 0
        a = arr + (size_t)f * NX * NY;
        c = bc[0]; fac = bf[0];
        edgeL = 0.0f; edgeR = 0.0f;
    } else if (row == PX - 1) {
        // bottom ghost row: affine of arr[f, NX-1, :], corners 0
        a = arr + ((size_t)f * NX + (NX - 1)) * NY;
        c = bc[1]; fac = bf[1];
        edgeL = 0.0f; edgeR = 0.0f;
    } else {
        // interior row: exact copy of arr[f, row-1, :], affine column ghosts
        a = arr + ((size_t)f * NX + (row - 1)) * NY;
        c = 0.0f; fac = 1.0f;                     // fma(1,x,0) == x exactly
        edgeL = fmaf(bf[2], a[0],      bc[2]);
        edgeR = fmaf(bf[3], a[NY - 1], bc[3]);
    }

    // Output row base offset = (f*PX + row) * 4098 -> always even.
    float* __restrict__ orow = out + ((size_t)f * PX + row) * PY;

    const int t = threadIdx.x;

    #pragma unroll
    for (int i = 0; i < 2; i++) {
        const int P = 4 * (t + i * THREADS);      // multiple of 4

        // Aligned 16B streaming load of a[P..P+3].
        const float4 A = __ldcs(reinterpret_cast<const float4*>(a + P));

        // a[P-1] = previous lane's A.w; lane 0 fetches it directly.
        float prev = __shfl_up_sync(0xffffffffu, A.w, 1);
        if ((t & 31) == 0) {
            prev = (P > 0) ? __ldcs(a + P - 1) : 0.0f;   // P==0 overridden below
        }

        float v0 = fmaf(fac, prev, c);
        if (P == 0) v0 = edgeL;                   // left edge (single thread)
        const float v1 = fmaf(fac, A.x, c);
        const float v2 = fmaf(fac, A.y, c);
        const float v3 = fmaf(fac, A.z, c);

        // 8B-aligned streaming stores at output positions P..P+3.
        __stcs(reinterpret_cast<float2*>(orow + P),     make_float2(v0, v1));
        __stcs(reinterpret_cast<float2*>(orow + P + 2), make_float2(v2, v3));

        // Tail pair: positions 4096 (fma of a[4095] = A.w) and 4097 (edgeR).
        if (i == 1 && t == THREADS - 1) {
            __stcs(reinterpret_cast<float2*>(orow + (PY - 2)),
                   make_float2(fmaf(fac, A.w, c), edgeR));
        }
    }
}

extern "C" void kernel_launch(void* const* d_in, const int* in_sizes, int n_in,
                              void* d_out, int out_size)
{
    const float* arr       = (const float*)d_in[0];
    const float* bc_const  = (const float*)d_in[1];
    const float* bc_factor = (const float*)d_in[2];
    float* out             = (float*)d_out;

    dim3 grid(PX, F);
    ghost_pad_kernel<<<grid, THREADS>>>(arr, bc_const, bc_factor, out);
}

// round 4
// speedup vs baseline: 1.1462x; 1.1462x over previous
#include <cuda_runtime.h>
#include <cstddef>

// Ghost-cell padding with affine boundary conditions.
// arr: (4, 4096, 4096) f32 -> out: (4, 4098, 4098) f32
//
// Unified row model: orow[0]=edgeL; orow[p]=fma(fac, a[p-1], c) for p=1..4096;
// orow[4097]=edgeR. Interior rows: (fac,c)=(1,0) (exact copy), edges = axis-1
// affine ghosts. Top/bottom rows: (fac,c)=bc[axis0,side], edges = 0 corners.
//
// The shift-by-one makes vector loads and vector stores mutually misaligned.
// Realign through shared memory: phase 1 stages the input row with perfect
// aligned LDG.128/STS.128; phase 2 reads the shifted values from smem (cheap
// 2-way-conflict LDS.32) and issues the same 8B-aligned STG.64 stores as the
// round-2 kernel. No shuffles, no divergent loads.

static constexpr int F  = 4;
static constexpr int NX = 4096;
static constexpr int NY = 4096;
static constexpr int PX = NX + 2;   // 4098
static constexpr int PY = NY + 2;   // 4098

static constexpr int THREADS = 512;

__global__ void __launch_bounds__(THREADS)
ghost_pad_kernel(const float* __restrict__ arr,
                 const float* __restrict__ bc,   // bc_const  flat [axis*2+side]
                 const float* __restrict__ bf,   // bc_factor flat [axis*2+side]
                 float* __restrict__ out)
{
    __shared__ float s[NY];         // staged input row (16 KB)

    const int row = blockIdx.x;     // 0 .. PX-1
    const int f   = blockIdx.y;     // field
    const int t   = threadIdx.x;

    // Source row pointer.
    const float* __restrict__ a;
    if (row == 0) {
        a = arr + (size_t)f * NX * NY;                    // arr[f, 0, :]
    } else if (row == PX - 1) {
        a = arr + ((size_t)f * NX + (NX - 1)) * NY;       // arr[f, NX-1, :]
    } else {
        a = arr + ((size_t)f * NX + (row - 1)) * NY;      // arr[f, row-1, :]
    }

    // Phase 1: stage the row into smem with aligned 16B loads/stores.
    #pragma unroll
    for (int i = 0; i < 2; i++) {
        const int k = 4 * (t + i * THREADS);              // 0..4092, mult of 4
        const float4 A = *reinterpret_cast<const float4*>(a + k);
        *reinterpret_cast<float4*>(s + k) = A;
    }
    __syncthreads();

    // Per-row affine coefficients and edge values (read edges from smem).
    float fac, c, edgeL, edgeR;
    if (row == 0) {
        c = bc[0]; fac = bf[0];
        edgeL = 0.0f; edgeR = 0.0f;
    } else if (row == PX - 1) {
        c = bc[1]; fac = bf[1];
        edgeL = 0.0f; edgeR = 0.0f;
    } else {
        c = 0.0f; fac = 1.0f;                             // fma(1,x,0) == x
        edgeL = fmaf(bf[2], s[0],      bc[2]);
        edgeR = fmaf(bf[3], s[NY - 1], bc[3]);
    }

    // Output row base offset = (f*PX + row) * 4098 -> always even,
    // so float2 stores at even j are 8B-aligned.
    float* __restrict__ orow = out + ((size_t)f * PX + row) * PY;

    // Phase 2: shifted read from smem, coalesced 8B stores.
    // Pairs (j, j+1), j = 2*(t + i*512) covers output 0..4095.
    #pragma unroll
    for (int i = 0; i < 4; i++) {
        const int j = 2 * (t + i * THREADS);
        const float l0 = s[(j == 0) ? 0 : (j - 1)];
        const float l1 = s[j];
        float v0 = fmaf(fac, l0, c);
        if (j == 0) v0 = edgeL;                           // single thread
        const float v1 = fmaf(fac, l1, c);
        *reinterpret_cast<float2*>(orow + j) = make_float2(v0, v1);
    }

    // Tail pair: positions 4096 (from a[4095]) and 4097 (right edge).
    if (t == 0) {
        *reinterpret_cast<float2*>(orow + (PY - 2)) =
            make_float2(fmaf(fac, s[NY - 1], c), edgeR);
    }
}

extern "C" void kernel_launch(void* const* d_in, const int* in_sizes, int n_in,
                              void* d_out, int out_size)
{
    const float* arr       = (const float*)d_in[0];
    const float* bc_const  = (const float*)d_in[1];
    const float* bc_factor = (const float*)d_in[2];
    float* out             = (float*)d_out;

    dim3 grid(PX, F);
    ghost_pad_kernel<<<grid, THREADS>>>(arr, bc_const, bc_factor, out);
}

// round 5
// speedup vs baseline: 1.1505x; 1.0037x over previous
#include <cuda_runtime.h>
#include <cstddef>

// Ghost-cell padding with affine boundary conditions.
// arr: (4, 4096, 4096) f32 -> out: (4, 4098, 4098) f32
//
// Round-5 change vs round-4 (single variable, clean attribution):
// add streaming cache hints (__ldcs on the global loads, __stcs on the
// global stores). Both streams are touch-once, 537 MB total vs 126 MB L2;
// the default allocate/LRU policy lets the read stream evict dirty store
// lines (and vice versa), degrading DRAM scheduling. Evict-first removes
// the thrash. Structure is otherwise identical to the 84.6 us round-4
// kernel (smem realignment, 8B-aligned float2 stores).

static constexpr int F  = 4;
static constexpr int NX = 4096;
static constexpr int NY = 4096;
static constexpr int PX = NX + 2;   // 4098
static constexpr int PY = NY + 2;   // 4098

static constexpr int THREADS = 512;

__global__ void __launch_bounds__(THREADS)
ghost_pad_kernel(const float* __restrict__ arr,
                 const float* __restrict__ bc,   // bc_const  flat [axis*2+side]
                 const float* __restrict__ bf,   // bc_factor flat [axis*2+side]
                 float* __restrict__ out)
{
    __shared__ float s[NY];         // staged input row (16 KB)

    const int row = blockIdx.x;     // 0 .. PX-1
    const int f   = blockIdx.y;     // field
    const int t   = threadIdx.x;

    // Source row pointer.
    const float* __restrict__ a;
    if (row == 0) {
        a = arr + (size_t)f * NX * NY;                    // arr[f, 0, :]
    } else if (row == PX - 1) {
        a = arr + ((size_t)f * NX + (NX - 1)) * NY;       // arr[f, NX-1, :]
    } else {
        a = arr + ((size_t)f * NX + (row - 1)) * NY;      // arr[f, row-1, :]
    }

    // Phase 1: stage the row into smem with aligned 16B streaming loads.
    #pragma unroll
    for (int i = 0; i < 2; i++) {
        const int k = 4 * (t + i * THREADS);              // 0..4092, mult of 4
        const float4 A = __ldcs(reinterpret_cast<const float4*>(a + k));
        *reinterpret_cast<float4*>(s + k) = A;
    }
    __syncthreads();

    // Per-row affine coefficients and edge values (edges read from smem).
    float fac, c, edgeL, edgeR;
    if (row == 0) {
        c = bc[0]; fac = bf[0];
        edgeL = 0.0f; edgeR = 0.0f;
    } else if (row == PX - 1) {
        c = bc[1]; fac = bf[1];
        edgeL = 0.0f; edgeR = 0.0f;
    } else {
        c = 0.0f; fac = 1.0f;                             // fma(1,x,0) == x
        edgeL = fmaf(bf[2], s[0],      bc[2]);
        edgeR = fmaf(bf[3], s[NY - 1], bc[3]);
    }

    // Output row base offset = (f*PX + row) * 4098 -> always even,
    // so float2 stores at even j are 8B-aligned.
    float* __restrict__ orow = out + ((size_t)f * PX + row) * PY;

    // Phase 2: shifted read from smem, coalesced 8B streaming stores.
    // Pairs (j, j+1), j = 2*(t + i*512) covers output 0..4095.
    #pragma unroll
    for (int i = 0; i < 4; i++) {
        const int j = 2 * (t + i * THREADS);
        const float l0 = s[(j == 0) ? 0 : (j - 1)];
        const float l1 = s[j];
        float v0 = fmaf(fac, l0, c);
        if (j == 0) v0 = edgeL;                           // single thread
        const float v1 = fmaf(fac, l1, c);
        __stcs(reinterpret_cast<float2*>(orow + j), make_float2(v0, v1));
    }

    // Tail pair: positions 4096 (from a[4095]) and 4097 (right edge).
    if (t == 0) {
        __stcs(reinterpret_cast<float2*>(orow + (PY - 2)),
               make_float2(fmaf(fac, s[NY - 1], c), edgeR));
    }
}

extern "C" void kernel_launch(void* const* d_in, const int* in_sizes, int n_in,
                              void* d_out, int out_size)
{
    const float* arr       = (const float*)d_in[0];
    const float* bc_const  = (const float*)d_in[1];
    const float* bc_factor = (const float*)d_in[2];
    float* out             = (float*)d_out;

    dim3 grid(PX, F);
    ghost_pad_kernel<<<grid, THREADS>>>(arr, bc_const, bc_factor, out);
}

// round 6
// speedup vs baseline: 1.2084x; 1.0504x over previous
#include <cuda_runtime.h>
#include <cstddef>

// Ghost-cell padding with affine boundary conditions.
// arr: (4, 4096, 4096) f32 -> out: (4, 4098, 4098) f32
//
// Round-6 change vs round-5 (single variable): process 2 padded rows per
// block. Each CTA now issues a 32 KB read burst (phase 1), one barrier, then
// a 32 KB write burst (phase 2), doubling the same-direction burst length
// seen by the DRAM controllers vs the 16/16 KB alternation of round 5 —
// targeting read<->write bus-turnaround loss, the remaining theorized binder
// at the 73%-of-spec DRAM plateau. Everything else (smem realignment,
// streaming hints, 8B-aligned float2 stores) is unchanged.

static constexpr int F  = 4;
static constexpr int NX = 4096;
static constexpr int NY = 4096;
static constexpr int PX = NX + 2;   // 4098
static constexpr int PY = NY + 2;   // 4098

static constexpr int THREADS = 512;
static constexpr int RPB     = 2;   // padded rows per block; 4098 = 2 * 2049

__global__ void __launch_bounds__(THREADS)
ghost_pad_kernel(const float* __restrict__ arr,
                 const float* __restrict__ bc,   // bc_const  flat [axis*2+side]
                 const float* __restrict__ bf,   // bc_factor flat [axis*2+side]
                 float* __restrict__ out)
{
    __shared__ float s[RPB][NY];    // staged input rows (32 KB)

    const int row0 = blockIdx.x * RPB;   // first padded row of this block
    const int f    = blockIdx.y;         // field
    const int t    = threadIdx.x;

    // Phase 1: stage RPB source rows into smem, aligned 16B streaming loads.
    #pragma unroll
    for (int rr = 0; rr < RPB; rr++) {
        const int row = row0 + rr;
        const int src = (row == 0) ? 0 : ((row == PX - 1) ? (NX - 1) : (row - 1));
        const float* __restrict__ a = arr + ((size_t)f * NX + src) * NY;
        #pragma unroll
        for (int i = 0; i < 2; i++) {
            const int k = 4 * (t + i * THREADS);          // 0..4092, mult of 4
            *reinterpret_cast<float4*>(&s[rr][k]) =
                __ldcs(reinterpret_cast<const float4*>(a + k));
        }
    }
    __syncthreads();

    // Phase 2: per row, shifted read from smem + coalesced 8B streaming stores.
    #pragma unroll
    for (int rr = 0; rr < RPB; rr++) {
        const int row = row0 + rr;

        float fac, c, edgeL, edgeR;
        if (row == 0) {
            c = bc[0]; fac = bf[0];                       // top ghost row
            edgeL = 0.0f; edgeR = 0.0f;
        } else if (row == PX - 1) {
            c = bc[1]; fac = bf[1];                       // bottom ghost row
            edgeL = 0.0f; edgeR = 0.0f;
        } else {
            c = 0.0f; fac = 1.0f;                         // fma(1,x,0) == x
            edgeL = fmaf(bf[2], s[rr][0],      bc[2]);
            edgeR = fmaf(bf[3], s[rr][NY - 1], bc[3]);
        }

        // Row base offset = (f*PX + row) * 4098 -> always even,
        // so float2 stores at even j are 8B-aligned.
        float* __restrict__ orow = out + ((size_t)f * PX + row) * PY;

        #pragma unroll
        for (int i = 0; i < 4; i++) {
            const int j = 2 * (t + i * THREADS);          // 0..4094, even
            const float l0 = s[rr][(j == 0) ? 0 : (j - 1)];
            const float l1 = s[rr][j];
            float v0 = fmaf(fac, l0, c);
            if (j == 0) v0 = edgeL;                       // single thread
            const float v1 = fmaf(fac, l1, c);
            __stcs(reinterpret_cast<float2*>(orow + j), make_float2(v0, v1));
        }

        // Tail pair: positions 4096 (from a[4095]) and 4097 (right edge).
        if (t == 0) {
            __stcs(reinterpret_cast<float2*>(orow + (PY - 2)),
                   make_float2(fmaf(fac, s[rr][NY - 1], c), edgeR));
        }
    }
}

extern "C" void kernel_launch(void* const* d_in, const int* in_sizes, int n_in,
                              void* d_out, int out_size)
{
    const float* arr       = (const float*)d_in[0];
    const float* bc_const  = (const float*)d_in[1];
    const float* bc_factor = (const float*)d_in[2];
    float* out             = (float*)d_out;

    dim3 grid(PX / RPB, F);         // 2049 x 4
    ghost_pad_kernel<<<grid, THREADS>>>(arr, bc_const, bc_factor, out);
}